// round 1
// baseline (speedup 1.0000x reference)
#include <cuda_runtime.h>

#define B 32
#define H 512
#define W 512
#define WPR 16               // 512 bits / 32 = 16 words per row
#define IMG_WORDS (H * WPR)  // 8192 words per image mask
#define ROWS 8               // rows per stats CTA

// ---- device scratch (no allocations allowed) ----
__device__ float    g_acc[B][12];            // 0:inter 1:psum 2:gsum 3:pe 4:ge 5:ie 6:pm 7:gm 8:im 9:pj 10:gj 11:ij
__device__ unsigned g_pmask[B * IMG_WORDS];  // pred > 0.5 bitmask
__device__ unsigned g_gmask[B * IMG_WORDS];  // gt   > 0.5 bitmask
__device__ float    g_dsum[B][2];            // [b][0]=p2g sum, [b][1]=g2p sum
__device__ float    g_dcnt[B][2];            // target pixel counts

__global__ void init_kernel() {
    int i = threadIdx.x;
    if (i < B * 12) ((float*)g_acc)[i] = 0.f;
}

// One CTA per (row-block, batch). 512 threads = one thread per column.
__global__ void stats_kernel(const float* __restrict__ pred, const float* __restrict__ gt) {
    __shared__ float sp[ROWS + 2][W];
    __shared__ float sg[ROWS + 2][W];
    __shared__ float sacc[12];

    const int x    = threadIdx.x;
    const int b    = blockIdx.y;
    const int row0 = blockIdx.x * ROWS;

    if (x < 12) sacc[x] = 0.f;

    const float* P = pred + (size_t)b * H * W;
    const float* G = gt   + (size_t)b * H * W;

    #pragma unroll
    for (int r = 0; r < ROWS + 2; r++) {
        int y = row0 - 1 + r;
        bool ok = ((unsigned)y < (unsigned)H);
        sp[r][x] = ok ? P[(size_t)y * W + x] : 0.f;
        sg[r][x] = ok ? G[(size_t)y * W + x] : 0.f;
    }
    __syncthreads();

    float a_i = 0.f, a_p = 0.f, a_g = 0.f;
    int c[9] = {0, 0, 0, 0, 0, 0, 0, 0, 0};

    #pragma unroll
    for (int j = 0; j < ROWS; j++) {
        int y = row0 + j;
        float p = sp[j + 1][x];
        float g = sg[j + 1][x];
        // 3x3 sum minus center (zero padding via guards)
        float pn = -p, gn = -g;
        #pragma unroll
        for (int r = 0; r < 3; r++) {
            pn += sp[j + r][x];
            gn += sg[j + r][x];
            if (x > 0)     { pn += sp[j + r][x - 1]; gn += sg[j + r][x - 1]; }
            if (x < W - 1) { pn += sp[j + r][x + 1]; gn += sg[j + r][x + 1]; }
        }
        bool pon = p > 0.5f, gon = g > 0.5f;
        int pe = (pn == 1.f) && pon, pm = (pn == 2.f) && pon, pj = (pn > 2.f) && pon;
        int ge = (gn == 1.f) && gon, gm = (gn == 2.f) && gon, gj = (gn > 2.f) && gon;

        a_i += p * g; a_p += p; a_g += g;
        c[0] += pe; c[1] += ge; c[2] += (pe & ge);
        c[3] += pm; c[4] += gm; c[5] += (pm & gm);
        c[6] += pj; c[7] += gj; c[8] += (pj & gj);

        unsigned pb = __ballot_sync(0xffffffffu, pon);
        unsigned gb = __ballot_sync(0xffffffffu, gon);
        if ((x & 31) == 0) {
            size_t widx = (size_t)(b * H + y) * WPR + (x >> 5);
            g_pmask[widx] = pb;
            g_gmask[widx] = gb;
        }
    }

    // warp-level reduce
    float f0 = a_i, f1 = a_p, f2 = a_g;
    #pragma unroll
    for (int o = 16; o; o >>= 1) {
        f0 += __shfl_down_sync(0xffffffffu, f0, o);
        f1 += __shfl_down_sync(0xffffffffu, f1, o);
        f2 += __shfl_down_sync(0xffffffffu, f2, o);
    }
    #pragma unroll
    for (int k = 0; k < 9; k++) {
        #pragma unroll
        for (int o = 16; o; o >>= 1) c[k] += __shfl_down_sync(0xffffffffu, c[k], o);
    }
    if ((x & 31) == 0) {
        atomicAdd(&sacc[0], f0);
        atomicAdd(&sacc[1], f1);
        atomicAdd(&sacc[2], f2);
        #pragma unroll
        for (int k = 0; k < 9; k++) atomicAdd(&sacc[3 + k], (float)c[k]);
    }
    __syncthreads();
    if (x < 12) atomicAdd(&g_acc[b][x], sacc[x]);
}

// One CTA per (batch, direction). 10 rounds of bit-packed 3x3 dilation in smem.
// dir 0: target = pred mask, reference = gt mask  (p2g)
// dir 1: target = gt mask,   reference = pred mask (g2p)
__global__ void medial_kernel() {
    extern __shared__ unsigned smem[];
    unsigned* cur = smem;
    unsigned* hor = smem + IMG_WORDS;
    unsigned* tgt = smem + 2 * IMG_WORDS;

    const int b   = blockIdx.x >> 1;
    const int dir = blockIdx.x & 1;
    const unsigned* ts = dir ? g_gmask : g_pmask;
    const unsigned* rs = dir ? g_pmask : g_gmask;
    const size_t base = (size_t)b * IMG_WORDS;

    for (int i = threadIdx.x; i < IMG_WORDS; i += blockDim.x) {
        tgt[i] = ts[base + i];
        cur[i] = rs[base + i];
    }
    __syncthreads();

    int dsum = 0;
    for (int d = 1; d <= 10; d++) {
        // horizontal dilation
        for (int i = threadIdx.x; i < IMG_WORDS; i += blockDim.x) {
            int cw = i & (WPR - 1);
            unsigned w  = cur[i];
            unsigned Lw = cw ? cur[i - 1] : 0u;
            unsigned Rw = (cw < WPR - 1) ? cur[i + 1] : 0u;
            hor[i] = w | (w << 1) | (w >> 1) | (Lw >> 31) | (Rw << 31);
        }
        __syncthreads();
        // vertical OR + newly-found accumulation
        for (int i = threadIdx.x; i < IMG_WORDS; i += blockDim.x) {
            int r = i >> 4;
            unsigned v = hor[i];
            if (r > 0)     v |= hor[i - WPR];
            if (r < H - 1) v |= hor[i + WPR];
            unsigned old = (d == 1) ? 0u : cur[i];
            dsum += d * __popc(tgt[i] & v & ~old);
            cur[i] = v;
        }
        __syncthreads();
    }
    int cnt = 0;
    for (int i = threadIdx.x; i < IMG_WORDS; i += blockDim.x) {
        dsum += 10 * __popc(tgt[i] & ~cur[i]);  // unfound -> MAX_DIST
        cnt  += __popc(tgt[i]);
    }

    // block reduce dsum, cnt (512 threads = 16 warps)
    __shared__ int w1[16], w2[16];
    #pragma unroll
    for (int o = 16; o; o >>= 1) {
        dsum += __shfl_down_sync(0xffffffffu, dsum, o);
        cnt  += __shfl_down_sync(0xffffffffu, cnt, o);
    }
    int wid = threadIdx.x >> 5;
    if ((threadIdx.x & 31) == 0) { w1[wid] = dsum; w2[wid] = cnt; }
    __syncthreads();
    if (threadIdx.x < 32) {
        int v1 = (threadIdx.x < 16) ? w1[threadIdx.x] : 0;
        int v2 = (threadIdx.x < 16) ? w2[threadIdx.x] : 0;
        #pragma unroll
        for (int o = 8; o; o >>= 1) {
            v1 += __shfl_down_sync(0xffffffffu, v1, o);
            v2 += __shfl_down_sync(0xffffffffu, v2, o);
        }
        if (threadIdx.x == 0) {
            g_dsum[b][dir] = (float)v1;
            g_dcnt[b][dir] = (float)v2;
        }
    }
}

__global__ void finalize_kernel(float* __restrict__ out) {
    __shared__ float sd[B], ss[B], sm2[B];
    int b = threadIdx.x;
    if (b < B) {
        float inter = g_acc[b][0], ps = g_acc[b][1], gs = g_acc[b][2];
        float dice = (2.f * inter + 1.f) / (ps + gs + 1.f);

        float pe = g_acc[b][3],  ge = g_acc[b][4],  ie = g_acc[b][5];
        float pm = g_acc[b][6],  gm = g_acc[b][7],  im = g_acc[b][8];
        float pj = g_acc[b][9],  gj = g_acc[b][10], ij = g_acc[b][11];
        float e_iou = (ie + 1.f) / (pe + ge - ie + 1.f);
        float m_iou = (im + 1.f) / (pm + gm - im + 1.f);
        float j_iou = (ij + 1.f) / (pj + gj - ij + 1.f);
        float total = ge + gj + gm + 1.f;
        float sl = 1.f - ((ge / total) * e_iou + (gj / total) * j_iou + (gm / total) * m_iou);

        float p2g = g_dsum[b][0] / (g_dcnt[b][0] + 1.f);
        float g2p = g_dsum[b][1] / (g_dcnt[b][1] + 1.f);
        float med = ((p2g + g2p) * 0.5f) / 10.f;

        sd[b] = dice; ss[b] = sl; sm2[b] = med;
    }
    __syncthreads();
    if (threadIdx.x == 0) {
        float d = 0.f, s = 0.f, m = 0.f;
        for (int i = 0; i < B; i++) { d += sd[i]; s += ss[i]; m += sm2[i]; }
        d *= (1.f / B); s *= (1.f / B); m *= (1.f / B);
        float dl = 1.f - d;                 // dice_loss
        float avg = (dl + s + m) / 3.f;
        out[0] = dl / (dl + 1.f) * avg + s / (s + 1.f) * avg + m / (m + 1.f) * avg;
    }
}

extern "C" void kernel_launch(void* const* d_in, const int* in_sizes, int n_in,
                              void* d_out, int out_size) {
    const float* pred = (const float*)d_in[0];
    const float* gt   = (const float*)d_in[1];
    float* out = (float*)d_out;

    (void)in_sizes; (void)n_in; (void)out_size;

    cudaFuncSetAttribute(medial_kernel, cudaFuncAttributeMaxDynamicSharedMemorySize,
                         3 * IMG_WORDS * (int)sizeof(unsigned));

    init_kernel<<<1, B * 12>>>();
    stats_kernel<<<dim3(H / ROWS, B), W>>>(pred, gt);
    medial_kernel<<<B * 2, 512, 3 * IMG_WORDS * sizeof(unsigned)>>>();
    finalize_kernel<<<1, 32>>>(out);
}

// round 2
// speedup vs baseline: 1.2764x; 1.2764x over previous
#include <cuda_runtime.h>

#define B 32
#define H 512
#define W 512
#define WPR 16                 // 512 bits / 32 = 16 words per row
#define ROWS 16                // rows per stats CTA
#define RB (H / ROWS)          // 32 row-blocks
#define BAND 128               // medial band height
#define HALO 10
#define BROWS (BAND + 2 * HALO)  // 148
#define NB (H / BAND)            // 4 bands
#define BWORDS (BROWS * WPR)     // 2368

// ---- device scratch (no allocations allowed) ----
__device__ unsigned g_pmask[B * H * WPR];
__device__ unsigned g_gmask[B * H * WPR];
__device__ float    g_part[RB][B][12];     // per row-block partials (no atomics)
__device__ int      g_mds [B][2][NB];      // medial distance sums per band
__device__ int      g_mcnt[B][2][NB];      // target counts per band

// One CTA per (row-block, batch). 512 threads = one thread per column.
// Dynamic smem: sp[(ROWS+2)*W], sg[(ROWS+2)*W].
__global__ void stats_kernel(const float* __restrict__ pred, const float* __restrict__ gt) {
    extern __shared__ float smem[];
    float* sp = smem;
    float* sg = smem + (ROWS + 2) * W;
    __shared__ float sacc[12];

    const int x    = threadIdx.x;
    const int b    = blockIdx.y;
    const int row0 = blockIdx.x * ROWS;

    if (x < 12) sacc[x] = 0.f;

    const float* P = pred + (size_t)b * H * W;
    const float* G = gt   + (size_t)b * H * W;

    #pragma unroll
    for (int r = 0; r < ROWS + 2; r++) {
        int y = row0 - 1 + r;
        bool ok = ((unsigned)y < (unsigned)H);
        sp[r * W + x] = ok ? P[(size_t)y * W + x] : 0.f;
        sg[r * W + x] = ok ? G[(size_t)y * W + x] : 0.f;
    }
    __syncthreads();

    const bool hasL = (x > 0), hasR = (x < W - 1);
    #define HS(s, r) (s[(r) * W + x] + (hasL ? s[(r) * W + x - 1] : 0.f) \
                                     + (hasR ? s[(r) * W + x + 1] : 0.f))

    float hp0 = HS(sp, 0), hp1 = HS(sp, 1);
    float hg0 = HS(sg, 0), hg1 = HS(sg, 1);

    float a_i = 0.f, a_p = 0.f, a_g = 0.f;
    int c[9] = {0, 0, 0, 0, 0, 0, 0, 0, 0};

    #pragma unroll
    for (int j = 0; j < ROWS; j++) {
        float hp2 = HS(sp, j + 2);
        float hg2 = HS(sg, j + 2);
        float p = sp[(j + 1) * W + x];
        float g = sg[(j + 1) * W + x];
        float pn = hp0 + hp1 + hp2 - p;
        float gn = hg0 + hg1 + hg2 - g;

        bool pon = p > 0.5f, gon = g > 0.5f;
        int pe = (pn == 1.f) && pon, pm = (pn == 2.f) && pon, pj = (pn > 2.f) && pon;
        int ge = (gn == 1.f) && gon, gm = (gn == 2.f) && gon, gj = (gn > 2.f) && gon;

        a_i += p * g; a_p += p; a_g += g;
        c[0] += pe; c[1] += ge; c[2] += (pe & ge);
        c[3] += pm; c[4] += gm; c[5] += (pm & gm);
        c[6] += pj; c[7] += gj; c[8] += (pj & gj);

        unsigned pb = __ballot_sync(0xffffffffu, pon);
        unsigned gb = __ballot_sync(0xffffffffu, gon);
        if ((x & 31) == 0) {
            size_t widx = (size_t)(b * H + row0 + j) * WPR + (x >> 5);
            g_pmask[widx] = pb;
            g_gmask[widx] = gb;
        }
        hp0 = hp1; hp1 = hp2; hg0 = hg1; hg1 = hg2;
    }
    #undef HS

    // warp-level reduce
    float f0 = a_i, f1 = a_p, f2 = a_g;
    #pragma unroll
    for (int o = 16; o; o >>= 1) {
        f0 += __shfl_down_sync(0xffffffffu, f0, o);
        f1 += __shfl_down_sync(0xffffffffu, f1, o);
        f2 += __shfl_down_sync(0xffffffffu, f2, o);
    }
    #pragma unroll
    for (int k = 0; k < 9; k++) {
        #pragma unroll
        for (int o = 16; o; o >>= 1) c[k] += __shfl_down_sync(0xffffffffu, c[k], o);
    }
    if ((x & 31) == 0) {
        atomicAdd(&sacc[0], f0);
        atomicAdd(&sacc[1], f1);
        atomicAdd(&sacc[2], f2);
        #pragma unroll
        for (int k = 0; k < 9; k++) atomicAdd(&sacc[3 + k], (float)c[k]);
    }
    __syncthreads();
    if (x < 12) g_part[blockIdx.x][b][x] = sacc[x];
}

// grid (NB, B*2). Each CTA: one row band (+10-row halo) of one (batch, direction).
// 10 rounds of bit-packed 3x3 dilation; band interior results are exact.
__global__ void medial_kernel() {
    __shared__ unsigned cur[BWORDS];
    __shared__ unsigned hor[BWORDS];
    __shared__ unsigned tgt[BWORDS];

    const int band = blockIdx.x;
    const int b    = blockIdx.y >> 1;
    const int dir  = blockIdx.y & 1;
    const unsigned* ts = dir ? g_gmask : g_pmask;
    const unsigned* rs = dir ? g_pmask : g_gmask;
    const int g0 = band * BAND - HALO;   // global row of local row 0

    for (int i = threadIdx.x; i < BWORDS; i += blockDim.x) {
        int r = g0 + (i >> 4);
        bool ok = ((unsigned)r < (unsigned)H);
        size_t gi = (size_t)(b * H + r) * WPR + (i & (WPR - 1));
        tgt[i] = ok ? ts[gi] : 0u;
        cur[i] = ok ? rs[gi] : 0u;
    }
    __syncthreads();

    int dsum = 0;
    for (int d = 1; d <= 10; d++) {
        for (int i = threadIdx.x; i < BWORDS; i += blockDim.x) {
            int cw = i & (WPR - 1);
            unsigned w = cur[i];
            unsigned L = cw ? cur[i - 1] : 0u;
            unsigned R = (cw < WPR - 1) ? cur[i + 1] : 0u;
            hor[i] = w | (w << 1) | (w >> 1) | (L >> 31) | (R << 31);
        }
        __syncthreads();
        for (int i = threadIdx.x; i < BWORDS; i += blockDim.x) {
            int r = i >> 4;
            unsigned v = hor[i];
            if (r > 0)         v |= hor[i - WPR];
            if (r < BROWS - 1) v |= hor[i + WPR];
            unsigned old = (d == 1) ? 0u : cur[i];
            if (r >= HALO && r < HALO + BAND)
                dsum += d * __popc(tgt[i] & v & ~old);
            cur[i] = v;
        }
        __syncthreads();
    }
    int cnt = 0;
    for (int i = threadIdx.x; i < BWORDS; i += blockDim.x) {
        int r = i >> 4;
        if (r >= HALO && r < HALO + BAND) {
            dsum += 10 * __popc(tgt[i] & ~cur[i]);   // unfound -> MAX_DIST
            cnt  += __popc(tgt[i]);
        }
    }

    // block reduce (512 threads = 16 warps)
    __shared__ int w1[16], w2[16];
    #pragma unroll
    for (int o = 16; o; o >>= 1) {
        dsum += __shfl_down_sync(0xffffffffu, dsum, o);
        cnt  += __shfl_down_sync(0xffffffffu, cnt, o);
    }
    int wid = threadIdx.x >> 5;
    if ((threadIdx.x & 31) == 0) { w1[wid] = dsum; w2[wid] = cnt; }
    __syncthreads();
    if (threadIdx.x < 32) {
        int v1 = (threadIdx.x < 16) ? w1[threadIdx.x] : 0;
        int v2 = (threadIdx.x < 16) ? w2[threadIdx.x] : 0;
        #pragma unroll
        for (int o = 8; o; o >>= 1) {
            v1 += __shfl_down_sync(0xffffffffu, v1, o);
            v2 += __shfl_down_sync(0xffffffffu, v2, o);
        }
        if (threadIdx.x == 0) {
            g_mds [b][dir][band] = v1;
            g_mcnt[b][dir][band] = v2;
        }
    }
}

__global__ void finalize_kernel(float* __restrict__ out) {
    __shared__ float acc[B][12];
    __shared__ float sd[B], ss[B], sm2[B];
    int t = threadIdx.x;

    if (t < B * 12) {
        int b = t / 12, k = t % 12;
        float s = 0.f;
        #pragma unroll 8
        for (int i = 0; i < RB; i++) s += g_part[i][b][k];
        acc[b][k] = s;
    }
    __syncthreads();

    if (t < B) {
        int b = t;
        float inter = acc[b][0], ps = acc[b][1], gs = acc[b][2];
        float dice = (2.f * inter + 1.f) / (ps + gs + 1.f);

        float pe = acc[b][3],  ge = acc[b][4],  ie = acc[b][5];
        float pm = acc[b][6],  gm = acc[b][7],  im = acc[b][8];
        float pj = acc[b][9],  gj = acc[b][10], ij = acc[b][11];
        float e_iou = (ie + 1.f) / (pe + ge - ie + 1.f);
        float m_iou = (im + 1.f) / (pm + gm - im + 1.f);
        float j_iou = (ij + 1.f) / (pj + gj - ij + 1.f);
        float total = ge + gj + gm + 1.f;
        float sl = 1.f - ((ge / total) * e_iou + (gj / total) * j_iou + (gm / total) * m_iou);

        int ds0 = 0, ds1 = 0, c0 = 0, c1 = 0;
        #pragma unroll
        for (int i = 0; i < NB; i++) {
            ds0 += g_mds[b][0][i];  c0 += g_mcnt[b][0][i];
            ds1 += g_mds[b][1][i];  c1 += g_mcnt[b][1][i];
        }
        float p2g = (float)ds0 / ((float)c0 + 1.f);
        float g2p = (float)ds1 / ((float)c1 + 1.f);
        float med = ((p2g + g2p) * 0.5f) / 10.f;

        sd[b] = dice; ss[b] = sl; sm2[b] = med;
    }
    __syncthreads();

    if (t == 0) {
        float d = 0.f, s = 0.f, m = 0.f;
        for (int i = 0; i < B; i++) { d += sd[i]; s += ss[i]; m += sm2[i]; }
        d *= (1.f / B); s *= (1.f / B); m *= (1.f / B);
        float dl = 1.f - d;                     // dice_loss
        float avg = (dl + s + m) / 3.f;
        out[0] = dl / (dl + 1.f) * avg + s / (s + 1.f) * avg + m / (m + 1.f) * avg;
    }
}

extern "C" void kernel_launch(void* const* d_in, const int* in_sizes, int n_in,
                              void* d_out, int out_size) {
    const float* pred = (const float*)d_in[0];
    const float* gt   = (const float*)d_in[1];
    float* out = (float*)d_out;
    (void)in_sizes; (void)n_in; (void)out_size;

    const int stats_smem = 2 * (ROWS + 2) * W * (int)sizeof(float);   // 73728 B
    cudaFuncSetAttribute(stats_kernel, cudaFuncAttributeMaxDynamicSharedMemorySize, stats_smem);

    stats_kernel<<<dim3(RB, B), W, stats_smem>>>(pred, gt);
    medial_kernel<<<dim3(NB, B * 2), 512>>>();
    finalize_kernel<<<1, 512>>>(out);
}

// round 3
// speedup vs baseline: 1.5920x; 1.2472x over previous
#include <cuda_runtime.h>

#define B 32
#define H 512
#define W 512
#define WPR 16                   // 512 bits / 32 = 16 words per row
#define STRIP 16                 // rows per warp (stats)
#define SPC 2                    // row-strips per CTA (stats)
#define GX (H / (STRIP * SPC))   // 16 stats CTAs in y-direction per batch

#define BAND 64                  // medial band height
#define HALO 10
#define BROWS (BAND + 2 * HALO)  // 84
#define NB (H / BAND)            // 8 bands
#define BWORDS (BROWS * WPR)     // 1344

// ---- device scratch (no allocations allowed) ----
__device__ unsigned g_pmask[B * H * WPR];
__device__ unsigned g_gmask[B * H * WPR];
__device__ float    g_part[GX][B][12];   // per-CTA partials (race-free)
__device__ int      g_mds [B][2][NB];
__device__ int      g_mcnt[B][2][NB];

struct RowH { float p[4]; float h[4]; };

__device__ __forceinline__ RowH load_row(const float* __restrict__ row, int x0, int lane) {
    RowH r;
    float4 v = *(const float4*)(row + x0);
    float Lp = __shfl_up_sync(0xffffffffu, v.w, 1);
    float Rp = __shfl_down_sync(0xffffffffu, v.x, 1);
    if (lane == 0)  Lp = (x0 > 0) ? __ldg(row + x0 - 1) : 0.f;
    if (lane == 31) Rp = (x0 + 4 < W) ? __ldg(row + x0 + 4) : 0.f;
    r.p[0] = v.x; r.p[1] = v.y; r.p[2] = v.z; r.p[3] = v.w;
    r.h[0] = Lp + v.x + v.y;
    r.h[1] = v.x + v.y + v.z;
    r.h[2] = v.y + v.z + v.w;
    r.h[3] = v.z + v.w + Rp;
    return r;
}

__device__ __forceinline__ RowH zero_row() {
    RowH r;
    #pragma unroll
    for (int i = 0; i < 4; i++) { r.p[i] = 0.f; r.h[i] = 0.f; }
    return r;
}

// grid (GX, B), block 256 = 8 warps. Warp w: colseg = w&3 (128 cols), substrip = w>>2.
// Fully warp-autonomous stencil: no smem tile, no syncs until the epilogue.
__global__ void __launch_bounds__(256) stats_kernel(const float* __restrict__ pred,
                                                    const float* __restrict__ gt) {
    const int lane = threadIdx.x & 31;
    const int wid  = threadIdx.x >> 5;
    const int cs   = wid & 3;
    const int ss   = wid >> 2;
    const int b    = blockIdx.y;
    const int y0   = (blockIdx.x * SPC + ss) * STRIP;
    const int x0   = cs * 128 + lane * 4;

    const float* P = pred + (size_t)b * H * W;
    const float* G = gt   + (size_t)b * H * W;

    RowH pp = (y0 > 0) ? load_row(P + (size_t)(y0 - 1) * W, x0, lane) : zero_row();
    RowH gp = (y0 > 0) ? load_row(G + (size_t)(y0 - 1) * W, x0, lane) : zero_row();
    RowH pc = load_row(P + (size_t)y0 * W, x0, lane);
    RowH gc = load_row(G + (size_t)y0 * W, x0, lane);

    float a_i = 0.f, a_p = 0.f, a_g = 0.f;
    int c[9] = {0, 0, 0, 0, 0, 0, 0, 0, 0};

    #pragma unroll 4
    for (int j = 0; j < STRIP; j++) {
        const int y = y0 + j;
        RowH pnx = (y + 1 < H) ? load_row(P + (size_t)(y + 1) * W, x0, lane) : zero_row();
        RowH gnx = (y + 1 < H) ? load_row(G + (size_t)(y + 1) * W, x0, lane) : zero_row();

        unsigned pnib = 0, gnib = 0;
        #pragma unroll
        for (int i = 0; i < 4; i++) {
            float pv = pc.p[i], gv = gc.p[i];
            float pn = pp.h[i] + pc.h[i] + pnx.h[i] - pv;
            float gn = gp.h[i] + gc.h[i] + gnx.h[i] - gv;
            bool pon = pv > 0.5f, gon = gv > 0.5f;
            int pe = pon && (pn == 1.f), pm = pon && (pn == 2.f), pj = pon && (pn > 2.f);
            int ge = gon && (gn == 1.f), gm = gon && (gn == 2.f), gj = gon && (gn > 2.f);
            a_i += pv * gv; a_p += pv; a_g += gv;
            c[0] += pe; c[1] += ge; c[2] += (pe & ge);
            c[3] += pm; c[4] += gm; c[5] += (pm & gm);
            c[6] += pj; c[7] += gj; c[8] += (pj & gj);
            pnib |= (unsigned)pon << i;
            gnib |= (unsigned)gon << i;
        }

        // assemble 32-bit mask words over 8-lane nibble groups
        unsigned pw = pnib << ((lane & 7) * 4);
        unsigned gw = gnib << ((lane & 7) * 4);
        pw |= __shfl_xor_sync(0xffffffffu, pw, 1);
        gw |= __shfl_xor_sync(0xffffffffu, gw, 1);
        pw |= __shfl_xor_sync(0xffffffffu, pw, 2);
        gw |= __shfl_xor_sync(0xffffffffu, gw, 2);
        pw |= __shfl_xor_sync(0xffffffffu, pw, 4);
        gw |= __shfl_xor_sync(0xffffffffu, gw, 4);
        if ((lane & 7) == 0) {
            size_t widx = (size_t)(b * H + y) * WPR + cs * 4 + (lane >> 3);
            g_pmask[widx] = pw;
            g_gmask[widx] = gw;
        }

        pp = pc; pc = pnx; gp = gc; gc = gnx;
    }

    // warp reduce 12 values
    #pragma unroll
    for (int o = 16; o; o >>= 1) {
        a_i += __shfl_down_sync(0xffffffffu, a_i, o);
        a_p += __shfl_down_sync(0xffffffffu, a_p, o);
        a_g += __shfl_down_sync(0xffffffffu, a_g, o);
    }
    #pragma unroll
    for (int k = 0; k < 9; k++) {
        #pragma unroll
        for (int o = 16; o; o >>= 1) c[k] += __shfl_down_sync(0xffffffffu, c[k], o);
    }

    __shared__ float sf[3];
    __shared__ int   si[9];
    if (threadIdx.x < 3) sf[threadIdx.x] = 0.f;
    if (threadIdx.x < 9) si[threadIdx.x] = 0;
    __syncthreads();
    if (lane == 0) {
        atomicAdd(&sf[0], a_i); atomicAdd(&sf[1], a_p); atomicAdd(&sf[2], a_g);
        #pragma unroll
        for (int k = 0; k < 9; k++) atomicAdd(&si[k], c[k]);
    }
    __syncthreads();
    if (threadIdx.x < 3)  g_part[blockIdx.x][b][threadIdx.x] = sf[threadIdx.x];
    if (threadIdx.x >= 3 && threadIdx.x < 12)
        g_part[blockIdx.x][b][threadIdx.x] = (float)si[threadIdx.x - 3];
}

// grid (NB, B*2), block 256. One 64-row band (+10-row halo) per CTA.
__global__ void __launch_bounds__(256) medial_kernel() {
    __shared__ unsigned cur[BWORDS];
    __shared__ unsigned hor[BWORDS];
    __shared__ unsigned tgt[BWORDS];

    const int band = blockIdx.x;
    const int b    = blockIdx.y >> 1;
    const int dir  = blockIdx.y & 1;
    const unsigned* ts = dir ? g_gmask : g_pmask;
    const unsigned* rs = dir ? g_pmask : g_gmask;
    const int g0 = band * BAND - HALO;

    for (int i = threadIdx.x; i < BWORDS; i += blockDim.x) {
        int r = g0 + (i >> 4);
        bool ok = ((unsigned)r < (unsigned)H);
        size_t gi = (size_t)(b * H + r) * WPR + (i & (WPR - 1));
        tgt[i] = ok ? ts[gi] : 0u;
        cur[i] = ok ? rs[gi] : 0u;
    }
    __syncthreads();

    int dsum = 0;
    for (int d = 1; d <= 10; d++) {
        for (int i = threadIdx.x; i < BWORDS; i += blockDim.x) {
            int cw = i & (WPR - 1);
            unsigned w = cur[i];
            unsigned L = cw ? cur[i - 1] : 0u;
            unsigned R = (cw < WPR - 1) ? cur[i + 1] : 0u;
            hor[i] = w | (w << 1) | (w >> 1) | (L >> 31) | (R << 31);
        }
        __syncthreads();
        for (int i = threadIdx.x; i < BWORDS; i += blockDim.x) {
            int r = i >> 4;
            unsigned v = hor[i];
            if (r > 0)         v |= hor[i - WPR];
            if (r < BROWS - 1) v |= hor[i + WPR];
            unsigned old = (d == 1) ? 0u : cur[i];
            if (r >= HALO && r < HALO + BAND)
                dsum += d * __popc(tgt[i] & v & ~old);
            cur[i] = v;
        }
        __syncthreads();
    }
    int cnt = 0;
    for (int i = threadIdx.x; i < BWORDS; i += blockDim.x) {
        int r = i >> 4;
        if (r >= HALO && r < HALO + BAND) {
            dsum += 10 * __popc(tgt[i] & ~cur[i]);   // unfound -> MAX_DIST
            cnt  += __popc(tgt[i]);
        }
    }

    __shared__ int w1[8], w2[8];
    #pragma unroll
    for (int o = 16; o; o >>= 1) {
        dsum += __shfl_down_sync(0xffffffffu, dsum, o);
        cnt  += __shfl_down_sync(0xffffffffu, cnt, o);
    }
    int wid = threadIdx.x >> 5;
    if ((threadIdx.x & 31) == 0) { w1[wid] = dsum; w2[wid] = cnt; }
    __syncthreads();
    if (threadIdx.x < 32) {
        int v1 = (threadIdx.x < 8) ? w1[threadIdx.x] : 0;
        int v2 = (threadIdx.x < 8) ? w2[threadIdx.x] : 0;
        #pragma unroll
        for (int o = 4; o; o >>= 1) {
            v1 += __shfl_down_sync(0xffffffffu, v1, o);
            v2 += __shfl_down_sync(0xffffffffu, v2, o);
        }
        if (threadIdx.x == 0) {
            g_mds [b][dir][band] = v1;
            g_mcnt[b][dir][band] = v2;
        }
    }
}

__global__ void finalize_kernel(float* __restrict__ out) {
    __shared__ float acc[B][12];
    __shared__ float sd[B], ss[B], sm2[B];
    int t = threadIdx.x;

    if (t < B * 12) {
        int b = t / 12, k = t % 12;
        float s = 0.f;
        #pragma unroll
        for (int i = 0; i < GX; i++) s += g_part[i][b][k];
        acc[b][k] = s;
    }
    __syncthreads();

    if (t < B) {
        int b = t;
        float inter = acc[b][0], ps = acc[b][1], gs = acc[b][2];
        float dice = (2.f * inter + 1.f) / (ps + gs + 1.f);

        float pe = acc[b][3],  ge = acc[b][4],  ie = acc[b][5];
        float pm = acc[b][6],  gm = acc[b][7],  im = acc[b][8];
        float pj = acc[b][9],  gj = acc[b][10], ij = acc[b][11];
        float e_iou = (ie + 1.f) / (pe + ge - ie + 1.f);
        float m_iou = (im + 1.f) / (pm + gm - im + 1.f);
        float j_iou = (ij + 1.f) / (pj + gj - ij + 1.f);
        float total = ge + gj + gm + 1.f;
        float sl = 1.f - ((ge / total) * e_iou + (gj / total) * j_iou + (gm / total) * m_iou);

        int ds0 = 0, ds1 = 0, c0 = 0, c1 = 0;
        #pragma unroll
        for (int i = 0; i < NB; i++) {
            ds0 += g_mds[b][0][i];  c0 += g_mcnt[b][0][i];
            ds1 += g_mds[b][1][i];  c1 += g_mcnt[b][1][i];
        }
        float p2g = (float)ds0 / ((float)c0 + 1.f);
        float g2p = (float)ds1 / ((float)c1 + 1.f);
        float med = ((p2g + g2p) * 0.5f) / 10.f;

        sd[b] = dice; ss[b] = sl; sm2[b] = med;
    }
    __syncthreads();

    if (t == 0) {
        float d = 0.f, s = 0.f, m = 0.f;
        for (int i = 0; i < B; i++) { d += sd[i]; s += ss[i]; m += sm2[i]; }
        d *= (1.f / B); s *= (1.f / B); m *= (1.f / B);
        float dl = 1.f - d;                      // dice_loss
        float avg = (dl + s + m) / 3.f;
        out[0] = dl / (dl + 1.f) * avg + s / (s + 1.f) * avg + m / (m + 1.f) * avg;
    }
}

extern "C" void kernel_launch(void* const* d_in, const int* in_sizes, int n_in,
                              void* d_out, int out_size) {
    const float* pred = (const float*)d_in[0];
    const float* gt   = (const float*)d_in[1];
    float* out = (float*)d_out;
    (void)in_sizes; (void)n_in; (void)out_size;

    stats_kernel<<<dim3(GX, B), 256>>>(pred, gt);
    medial_kernel<<<dim3(NB, B * 2), 256>>>();
    finalize_kernel<<<1, 512>>>(out);
}

// round 4
// speedup vs baseline: 1.9191x; 1.2055x over previous
#include <cuda_runtime.h>

#define B 32
#define H 512
#define W 512
#define WPR 16                   // 512 bits / 32 = 16 words per row
#define STRIP 32                 // rows per warp (stats)
#define GX (H / STRIP)           // 16 stats row-blocks per batch

#define BAND 64                  // medial band height
#define HALO 10
#define BROWS (BAND + 2 * HALO)  // 84
#define NB (H / BAND)            // 8 bands
#define BWORDS (BROWS * WPR)     // 1344
#define MEDIAL_BLOCKS (NB * B * 2)

// ---- device scratch (no allocations allowed) ----
__device__ unsigned g_pmask[B * H * WPR];
__device__ unsigned g_gmask[B * H * WPR];
__device__ float    g_part[GX][B][12];   // per-CTA stats partials (race-free)
__device__ int      g_mds [B][2][NB];
__device__ int      g_mcnt[B][2][NB];
__device__ int      g_done = 0;          // last-block counter (self-resetting)

struct Raw { float4 v; float eL, eR; };

// Issue raw loads for one row (float4 + predicated edge scalars). No shuffles here,
// so consumption can be deferred -> deep MLP.
__device__ __forceinline__ Raw load_raw(const float* __restrict__ rowptr,
                                        int lane, int x0, bool ok) {
    Raw r;
    if (ok) {
        r.v  = *(const float4*)rowptr;
        r.eL = (lane == 0  && x0 > 0)     ? __ldg(rowptr - 1) : 0.f;
        r.eR = (lane == 31 && x0 + 4 < W) ? __ldg(rowptr + 4) : 0.f;
    } else {
        r.v = make_float4(0.f, 0.f, 0.f, 0.f);
        r.eL = r.eR = 0.f;
    }
    return r;
}

struct RowH { float p[4]; float h[4]; };

__device__ __forceinline__ RowH convert(const Raw& r, int lane) {
    float Lp = __shfl_up_sync(0xffffffffu, r.v.w, 1);
    float Rp = __shfl_down_sync(0xffffffffu, r.v.x, 1);
    if (lane == 0)  Lp = r.eL;
    if (lane == 31) Rp = r.eR;
    RowH o;
    o.p[0] = r.v.x; o.p[1] = r.v.y; o.p[2] = r.v.z; o.p[3] = r.v.w;
    o.h[0] = Lp + r.v.x + r.v.y;
    o.h[1] = r.v.x + r.v.y + r.v.z;
    o.h[2] = r.v.y + r.v.z + r.v.w;
    o.h[3] = r.v.z + r.v.w + Rp;
    return o;
}

// grid (GX, B), block 128 = 4 warps, warp w owns 128-col segment, STRIP rows.
// Warp-autonomous; 2-row raw prefetch pipeline; incremental row pointers.
__global__ void __launch_bounds__(128) stats_kernel(const float* __restrict__ pred,
                                                    const float* __restrict__ gt) {
    const int lane = threadIdx.x & 31;
    const int cs   = threadIdx.x >> 5;     // column segment 0..3
    const int b    = blockIdx.y;
    const int y0   = blockIdx.x * STRIP;
    const int x0   = cs * 128 + lane * 4;

    const float* Pp = pred + (size_t)b * H * W + x0 + (size_t)(y0 - 1) * W;
    const float* Gp = gt   + (size_t)b * H * W + x0 + (size_t)(y0 - 1) * W;

    // prologue: h-rows for y0-1, y0; raw rows y0+1, y0+2 in flight
    Raw rp = load_raw(Pp, lane, x0, y0 > 0);
    Raw rg = load_raw(Gp, lane, x0, y0 > 0);
    Pp += W; Gp += W;
    Raw rp0 = load_raw(Pp, lane, x0, true);
    Raw rg0 = load_raw(Gp, lane, x0, true);
    Pp += W; Gp += W;
    Raw vP1 = load_raw(Pp, lane, x0, y0 + 1 < H);
    Raw vG1 = load_raw(Gp, lane, x0, y0 + 1 < H);
    Pp += W; Gp += W;
    Raw vP2 = load_raw(Pp, lane, x0, y0 + 2 < H);
    Raw vG2 = load_raw(Gp, lane, x0, y0 + 2 < H);
    Pp += W; Gp += W;

    RowH ppr = convert(rp, lane);
    RowH gpr = convert(rg, lane);
    float pph[4] = { ppr.h[0], ppr.h[1], ppr.h[2], ppr.h[3] };
    float gph[4] = { gpr.h[0], gpr.h[1], gpr.h[2], gpr.h[3] };
    RowH pc = convert(rp0, lane);
    RowH gc = convert(rg0, lane);

    float a_i = 0.f, a_p = 0.f, a_g = 0.f;
    int c[9] = {0, 0, 0, 0, 0, 0, 0, 0, 0};

    #pragma unroll 4
    for (int j = 0; j < STRIP; j++) {
        const int y = y0 + j;
        // issue loads for row y+3 (consumed two iterations later)
        Raw vPn = load_raw(Pp, lane, x0, y + 3 < H);
        Raw vGn = load_raw(Gp, lane, x0, y + 3 < H);
        Pp += W; Gp += W;

        RowH pnx = convert(vP1, lane);   // row y+1
        RowH gnx = convert(vG1, lane);

        unsigned pnib = 0, gnib = 0;
        #pragma unroll
        for (int i = 0; i < 4; i++) {
            float pv = pc.p[i], gv = gc.p[i];
            float pn = pph[i] + pc.h[i] + pnx.h[i] - pv;
            float gn = gph[i] + gc.h[i] + gnx.h[i] - gv;
            bool pon = pv > 0.5f, gon = gv > 0.5f;
            int pe = pon && (pn == 1.f), pm = pon && (pn == 2.f), pj = pon && (pn > 2.f);
            int ge = gon && (gn == 1.f), gm = gon && (gn == 2.f), gj = gon && (gn > 2.f);
            a_i += pv * gv; a_p += pv; a_g += gv;
            c[0] += pe; c[1] += ge; c[2] += (pe & ge);
            c[3] += pm; c[4] += gm; c[5] += (pm & gm);
            c[6] += pj; c[7] += gj; c[8] += (pj & gj);
            pnib |= (unsigned)pon << i;
            gnib |= (unsigned)gon << i;
        }

        // assemble 32-bit mask words over 8-lane nibble groups
        unsigned pw = pnib << ((lane & 7) * 4);
        unsigned gw = gnib << ((lane & 7) * 4);
        pw |= __shfl_xor_sync(0xffffffffu, pw, 1);
        gw |= __shfl_xor_sync(0xffffffffu, gw, 1);
        pw |= __shfl_xor_sync(0xffffffffu, pw, 2);
        gw |= __shfl_xor_sync(0xffffffffu, gw, 2);
        pw |= __shfl_xor_sync(0xffffffffu, pw, 4);
        gw |= __shfl_xor_sync(0xffffffffu, gw, 4);
        if ((lane & 7) == 0) {
            size_t widx = (size_t)(b * H + y) * WPR + cs * 4 + (lane >> 3);
            g_pmask[widx] = pw;
            g_gmask[widx] = gw;
        }

        // rotate pipeline
        #pragma unroll
        for (int i = 0; i < 4; i++) { pph[i] = pc.h[i]; gph[i] = gc.h[i]; }
        pc = pnx; gc = gnx;
        vP1 = vP2; vG1 = vG2;
        vP2 = vPn; vG2 = vGn;
    }

    // warp reduce 12 values
    #pragma unroll
    for (int o = 16; o; o >>= 1) {
        a_i += __shfl_down_sync(0xffffffffu, a_i, o);
        a_p += __shfl_down_sync(0xffffffffu, a_p, o);
        a_g += __shfl_down_sync(0xffffffffu, a_g, o);
    }
    #pragma unroll
    for (int k = 0; k < 9; k++) {
        #pragma unroll
        for (int o = 16; o; o >>= 1) c[k] += __shfl_down_sync(0xffffffffu, c[k], o);
    }

    __shared__ float sf[3];
    __shared__ int   si[9];
    if (threadIdx.x < 3) sf[threadIdx.x] = 0.f;
    if (threadIdx.x < 9) si[threadIdx.x] = 0;
    __syncthreads();
    if (lane == 0) {
        atomicAdd(&sf[0], a_i); atomicAdd(&sf[1], a_p); atomicAdd(&sf[2], a_g);
        #pragma unroll
        for (int k = 0; k < 9; k++) atomicAdd(&si[k], c[k]);
    }
    __syncthreads();
    if (threadIdx.x < 3)  g_part[blockIdx.x][b][threadIdx.x] = sf[threadIdx.x];
    if (threadIdx.x >= 3 && threadIdx.x < 12)
        g_part[blockIdx.x][b][threadIdx.x] = (float)si[threadIdx.x - 3];
}

// grid (NB, B*2), block 256. One 64-row band (+10-row halo) per CTA.
// Last finishing CTA performs the scalar finalize (fused; counter self-resets).
__global__ void __launch_bounds__(256) medial_kernel(float* __restrict__ out) {
    __shared__ unsigned cur[BWORDS];
    __shared__ unsigned hor[BWORDS];
    __shared__ unsigned tgt[BWORDS];

    const int band = blockIdx.x;
    const int b    = blockIdx.y >> 1;
    const int dir  = blockIdx.y & 1;
    const unsigned* ts = dir ? g_gmask : g_pmask;
    const unsigned* rs = dir ? g_pmask : g_gmask;
    const int g0 = band * BAND - HALO;

    for (int i = threadIdx.x; i < BWORDS; i += blockDim.x) {
        int r = g0 + (i >> 4);
        bool ok = ((unsigned)r < (unsigned)H);
        size_t gi = (size_t)(b * H + r) * WPR + (i & (WPR - 1));
        tgt[i] = ok ? ts[gi] : 0u;
        cur[i] = ok ? rs[gi] : 0u;
    }
    __syncthreads();

    int dsum = 0;
    for (int d = 1; d <= 10; d++) {
        for (int i = threadIdx.x; i < BWORDS; i += blockDim.x) {
            int cw = i & (WPR - 1);
            unsigned w = cur[i];
            unsigned L = cw ? cur[i - 1] : 0u;
            unsigned R = (cw < WPR - 1) ? cur[i + 1] : 0u;
            hor[i] = w | (w << 1) | (w >> 1) | (L >> 31) | (R << 31);
        }
        __syncthreads();
        for (int i = threadIdx.x; i < BWORDS; i += blockDim.x) {
            int r = i >> 4;
            unsigned v = hor[i];
            if (r > 0)         v |= hor[i - WPR];
            if (r < BROWS - 1) v |= hor[i + WPR];
            unsigned old = (d == 1) ? 0u : cur[i];
            if (r >= HALO && r < HALO + BAND)
                dsum += d * __popc(tgt[i] & v & ~old);
            cur[i] = v;
        }
        __syncthreads();
    }
    int cnt = 0;
    for (int i = threadIdx.x; i < BWORDS; i += blockDim.x) {
        int r = i >> 4;
        if (r >= HALO && r < HALO + BAND) {
            dsum += 10 * __popc(tgt[i] & ~cur[i]);   // unfound -> MAX_DIST
            cnt  += __popc(tgt[i]);
        }
    }

    __shared__ int w1[8], w2[8];
    #pragma unroll
    for (int o = 16; o; o >>= 1) {
        dsum += __shfl_down_sync(0xffffffffu, dsum, o);
        cnt  += __shfl_down_sync(0xffffffffu, cnt, o);
    }
    int wid = threadIdx.x >> 5;
    if ((threadIdx.x & 31) == 0) { w1[wid] = dsum; w2[wid] = cnt; }
    __syncthreads();
    if (threadIdx.x < 32) {
        int v1 = (threadIdx.x < 8) ? w1[threadIdx.x] : 0;
        int v2 = (threadIdx.x < 8) ? w2[threadIdx.x] : 0;
        #pragma unroll
        for (int o = 4; o; o >>= 1) {
            v1 += __shfl_down_sync(0xffffffffu, v1, o);
            v2 += __shfl_down_sync(0xffffffffu, v2, o);
        }
        if (threadIdx.x == 0) {
            g_mds [b][dir][band] = v1;
            g_mcnt[b][dir][band] = v2;
        }
    }

    // ---- last-block finalize ----
    __shared__ bool isLast;
    __syncthreads();
    if (threadIdx.x == 0) {
        __threadfence();
        int old = atomicAdd(&g_done, 1);
        isLast = (old == MEDIAL_BLOCKS - 1);
    }
    __syncthreads();
    if (!isLast) return;
    __threadfence();

    __shared__ float acc[B][12];
    __shared__ float sd[B], ss[B], sm2[B];
    int t = threadIdx.x;
    for (int idx = t; idx < B * 12; idx += 256) {
        int bb = idx / 12, k = idx % 12;
        float s = 0.f;
        #pragma unroll
        for (int i = 0; i < GX; i++) s += g_part[i][bb][k];
        acc[bb][k] = s;
    }
    __syncthreads();

    if (t < B) {
        int bb = t;
        float inter = acc[bb][0], ps = acc[bb][1], gs = acc[bb][2];
        float dice = (2.f * inter + 1.f) / (ps + gs + 1.f);

        float pe = acc[bb][3],  ge = acc[bb][4],  ie = acc[bb][5];
        float pm = acc[bb][6],  gm = acc[bb][7],  im = acc[bb][8];
        float pj = acc[bb][9],  gj = acc[bb][10], ij = acc[bb][11];
        float e_iou = (ie + 1.f) / (pe + ge - ie + 1.f);
        float m_iou = (im + 1.f) / (pm + gm - im + 1.f);
        float j_iou = (ij + 1.f) / (pj + gj - ij + 1.f);
        float total = ge + gj + gm + 1.f;
        float sl = 1.f - ((ge / total) * e_iou + (gj / total) * j_iou + (gm / total) * m_iou);

        int ds0 = 0, ds1 = 0, c0 = 0, c1 = 0;
        #pragma unroll
        for (int i = 0; i < NB; i++) {
            ds0 += g_mds[bb][0][i];  c0 += g_mcnt[bb][0][i];
            ds1 += g_mds[bb][1][i];  c1 += g_mcnt[bb][1][i];
        }
        float p2g = (float)ds0 / ((float)c0 + 1.f);
        float g2p = (float)ds1 / ((float)c1 + 1.f);
        float med = ((p2g + g2p) * 0.5f) / 10.f;

        sd[bb] = dice; ss[bb] = sl; sm2[bb] = med;
    }
    __syncthreads();

    if (t == 0) {
        float d = 0.f, s = 0.f, m = 0.f;
        for (int i = 0; i < B; i++) { d += sd[i]; s += ss[i]; m += sm2[i]; }
        d *= (1.f / B); s *= (1.f / B); m *= (1.f / B);
        float dl = 1.f - d;                      // dice_loss
        float avg = (dl + s + m) / 3.f;
        out[0] = dl / (dl + 1.f) * avg + s / (s + 1.f) * avg + m / (m + 1.f) * avg;
        g_done = 0;                              // reset for next graph replay
    }
}

extern "C" void kernel_launch(void* const* d_in, const int* in_sizes, int n_in,
                              void* d_out, int out_size) {
    const float* pred = (const float*)d_in[0];
    const float* gt   = (const float*)d_in[1];
    float* out = (float*)d_out;
    (void)in_sizes; (void)n_in; (void)out_size;

    stats_kernel<<<dim3(GX, B), 128>>>(pred, gt);
    medial_kernel<<<dim3(NB, B * 2), 256>>>(out);
}

// round 5
// speedup vs baseline: 2.0402x; 1.0631x over previous
#include <cuda_runtime.h>

#define B 32
#define H 512
#define W 512
#define WPR 16                   // 512 bits / 32 = 16 words per row
#define STRIP 32                 // rows per warp (stats)
#define GX (H / STRIP)           // 16 stats row-blocks per batch

#define MBAND 256                // medial interior rows per CTA
#define MNB (H / MBAND)          // 2 bands
#define MWARPS 10                // 8 interior + 2 halo warps
#define MEDIAL_BLOCKS (MNB * B * 2)

// ---- device scratch (no allocations allowed) ----
__device__ unsigned g_pmask[B * H * WPR];
__device__ unsigned g_gmask[B * H * WPR];
__device__ float    g_part[GX][B][12];   // per-CTA stats partials (race-free)
__device__ int      g_mds [B][2][MNB];
__device__ int      g_mcnt[B][2][MNB];
__device__ int      g_done = 0;          // last-block counter (self-resetting)

// ======================= stats (unchanged from R4) =======================
struct Raw { float4 v; float eL, eR; };

__device__ __forceinline__ Raw load_raw(const float* __restrict__ rowptr,
                                        int lane, int x0, bool ok) {
    Raw r;
    if (ok) {
        r.v  = *(const float4*)rowptr;
        r.eL = (lane == 0  && x0 > 0)     ? __ldg(rowptr - 1) : 0.f;
        r.eR = (lane == 31 && x0 + 4 < W) ? __ldg(rowptr + 4) : 0.f;
    } else {
        r.v = make_float4(0.f, 0.f, 0.f, 0.f);
        r.eL = r.eR = 0.f;
    }
    return r;
}

struct RowH { float p[4]; float h[4]; };

__device__ __forceinline__ RowH convert(const Raw& r, int lane) {
    float Lp = __shfl_up_sync(0xffffffffu, r.v.w, 1);
    float Rp = __shfl_down_sync(0xffffffffu, r.v.x, 1);
    if (lane == 0)  Lp = r.eL;
    if (lane == 31) Rp = r.eR;
    RowH o;
    o.p[0] = r.v.x; o.p[1] = r.v.y; o.p[2] = r.v.z; o.p[3] = r.v.w;
    o.h[0] = Lp + r.v.x + r.v.y;
    o.h[1] = r.v.x + r.v.y + r.v.z;
    o.h[2] = r.v.y + r.v.z + r.v.w;
    o.h[3] = r.v.z + r.v.w + Rp;
    return o;
}

__global__ void __launch_bounds__(128) stats_kernel(const float* __restrict__ pred,
                                                    const float* __restrict__ gt) {
    const int lane = threadIdx.x & 31;
    const int cs   = threadIdx.x >> 5;
    const int b    = blockIdx.y;
    const int y0   = blockIdx.x * STRIP;
    const int x0   = cs * 128 + lane * 4;

    const float* Pp = pred + (size_t)b * H * W + x0 + (size_t)(y0 - 1) * W;
    const float* Gp = gt   + (size_t)b * H * W + x0 + (size_t)(y0 - 1) * W;

    Raw rp = load_raw(Pp, lane, x0, y0 > 0);
    Raw rg = load_raw(Gp, lane, x0, y0 > 0);
    Pp += W; Gp += W;
    Raw rp0 = load_raw(Pp, lane, x0, true);
    Raw rg0 = load_raw(Gp, lane, x0, true);
    Pp += W; Gp += W;
    Raw vP1 = load_raw(Pp, lane, x0, y0 + 1 < H);
    Raw vG1 = load_raw(Gp, lane, x0, y0 + 1 < H);
    Pp += W; Gp += W;
    Raw vP2 = load_raw(Pp, lane, x0, y0 + 2 < H);
    Raw vG2 = load_raw(Gp, lane, x0, y0 + 2 < H);
    Pp += W; Gp += W;

    RowH ppr = convert(rp, lane);
    RowH gpr = convert(rg, lane);
    float pph[4] = { ppr.h[0], ppr.h[1], ppr.h[2], ppr.h[3] };
    float gph[4] = { gpr.h[0], gpr.h[1], gpr.h[2], gpr.h[3] };
    RowH pc = convert(rp0, lane);
    RowH gc = convert(rg0, lane);

    float a_i = 0.f, a_p = 0.f, a_g = 0.f;
    int c[9] = {0, 0, 0, 0, 0, 0, 0, 0, 0};

    #pragma unroll 4
    for (int j = 0; j < STRIP; j++) {
        const int y = y0 + j;
        Raw vPn = load_raw(Pp, lane, x0, y + 3 < H);
        Raw vGn = load_raw(Gp, lane, x0, y + 3 < H);
        Pp += W; Gp += W;

        RowH pnx = convert(vP1, lane);
        RowH gnx = convert(vG1, lane);

        unsigned pnib = 0, gnib = 0;
        #pragma unroll
        for (int i = 0; i < 4; i++) {
            float pv = pc.p[i], gv = gc.p[i];
            float pn = pph[i] + pc.h[i] + pnx.h[i] - pv;
            float gn = gph[i] + gc.h[i] + gnx.h[i] - gv;
            bool pon = pv > 0.5f, gon = gv > 0.5f;
            int pe = pon && (pn == 1.f), pm = pon && (pn == 2.f), pj = pon && (pn > 2.f);
            int ge = gon && (gn == 1.f), gm = gon && (gn == 2.f), gj = gon && (gn > 2.f);
            a_i += pv * gv; a_p += pv; a_g += gv;
            c[0] += pe; c[1] += ge; c[2] += (pe & ge);
            c[3] += pm; c[4] += gm; c[5] += (pm & gm);
            c[6] += pj; c[7] += gj; c[8] += (pj & gj);
            pnib |= (unsigned)pon << i;
            gnib |= (unsigned)gon << i;
        }

        unsigned pw = pnib << ((lane & 7) * 4);
        unsigned gw = gnib << ((lane & 7) * 4);
        pw |= __shfl_xor_sync(0xffffffffu, pw, 1);
        gw |= __shfl_xor_sync(0xffffffffu, gw, 1);
        pw |= __shfl_xor_sync(0xffffffffu, pw, 2);
        gw |= __shfl_xor_sync(0xffffffffu, gw, 2);
        pw |= __shfl_xor_sync(0xffffffffu, pw, 4);
        gw |= __shfl_xor_sync(0xffffffffu, gw, 4);
        if ((lane & 7) == 0) {
            size_t widx = (size_t)(b * H + y) * WPR + cs * 4 + (lane >> 3);
            g_pmask[widx] = pw;
            g_gmask[widx] = gw;
        }

        #pragma unroll
        for (int i = 0; i < 4; i++) { pph[i] = pc.h[i]; gph[i] = gc.h[i]; }
        pc = pnx; gc = gnx;
        vP1 = vP2; vG1 = vG2;
        vP2 = vPn; vG2 = vGn;
    }

    #pragma unroll
    for (int o = 16; o; o >>= 1) {
        a_i += __shfl_down_sync(0xffffffffu, a_i, o);
        a_p += __shfl_down_sync(0xffffffffu, a_p, o);
        a_g += __shfl_down_sync(0xffffffffu, a_g, o);
    }
    #pragma unroll
    for (int k = 0; k < 9; k++) {
        #pragma unroll
        for (int o = 16; o; o >>= 1) c[k] += __shfl_down_sync(0xffffffffu, c[k], o);
    }

    __shared__ float sf[3];
    __shared__ int   si[9];
    if (threadIdx.x < 3) sf[threadIdx.x] = 0.f;
    if (threadIdx.x < 9) si[threadIdx.x] = 0;
    __syncthreads();
    if (lane == 0) {
        atomicAdd(&sf[0], a_i); atomicAdd(&sf[1], a_p); atomicAdd(&sf[2], a_g);
        #pragma unroll
        for (int k = 0; k < 9; k++) atomicAdd(&si[k], c[k]);
    }
    __syncthreads();
    if (threadIdx.x < 3)  g_part[blockIdx.x][b][threadIdx.x] = sf[threadIdx.x];
    if (threadIdx.x >= 3 && threadIdx.x < 12)
        g_part[blockIdx.x][b][threadIdx.x] = (float)si[threadIdx.x - 3];
}

// ======================= medial: register-resident rows =======================
// grid (MNB, B*2), block 320 = 10 warps (warp 0 and 9 are vertical halo).
// Lane = row; 16 mask words per lane in registers. 9 dilation rounds:
//   dist_sum = popc(tgt) + sum_{d=1..9} popc(tgt & ~dil_d)
__global__ void __launch_bounds__(320) medial_kernel(float* __restrict__ out) {
    const int lane = threadIdx.x & 31;
    const int w    = threadIdx.x >> 5;
    const int band = blockIdx.x;
    const int b    = blockIdx.y >> 1;
    const int dir  = blockIdx.y & 1;
    const unsigned* ts = dir ? g_gmask : g_pmask;
    const unsigned* rs = dir ? g_pmask : g_gmask;

    const int r = band * MBAND + (w - 1) * 32 + lane;
    const bool valid    = ((unsigned)r < (unsigned)H);
    const bool interior = (w >= 1 && w <= 8);

    unsigned cur[16], tgt[16];
    #pragma unroll
    for (int i = 0; i < 16; i++) { cur[i] = 0u; tgt[i] = 0u; }
    if (valid) {
        const uint4* cp = reinterpret_cast<const uint4*>(rs + ((size_t)b * H + r) * WPR);
        const uint4* tp = reinterpret_cast<const uint4*>(ts + ((size_t)b * H + r) * WPR);
        #pragma unroll
        for (int j = 0; j < 4; j++) {
            uint4 c4 = cp[j];
            cur[4*j+0] = c4.x; cur[4*j+1] = c4.y; cur[4*j+2] = c4.z; cur[4*j+3] = c4.w;
            uint4 t4 = tp[j];
            tgt[4*j+0] = t4.x; tgt[4*j+1] = t4.y; tgt[4*j+2] = t4.z; tgt[4*j+3] = t4.w;
        }
    }

    int cnt = 0, notcov = 0;
    if (interior) {
        #pragma unroll
        for (int i = 0; i < 16; i++) cnt += __popc(tgt[i]);
    }

    __shared__ unsigned s_top[2][MWARPS][16];
    __shared__ unsigned s_bot[2][MWARPS][16];

    for (int d = 1; d <= 9; d++) {
        unsigned hor[16];
        #pragma unroll
        for (int i = 0; i < 16; i++) {
            unsigned x = cur[i];
            unsigned h = x | (x << 1) | (x >> 1);
            if (i > 0)  h |= cur[i - 1] >> 31;
            if (i < 15) h |= cur[i + 1] << 31;
            hor[i] = h;
        }
        const int buf = d & 1;
        if (lane == 0) {
            #pragma unroll
            for (int i = 0; i < 16; i++) s_top[buf][w][i] = hor[i];
        }
        if (lane == 31) {
            #pragma unroll
            for (int i = 0; i < 16; i++) s_bot[buf][w][i] = hor[i];
        }
        __syncthreads();
        #pragma unroll
        for (int i = 0; i < 16; i++) {
            unsigned up = __shfl_up_sync(0xffffffffu, hor[i], 1);
            unsigned dn = __shfl_down_sync(0xffffffffu, hor[i], 1);
            if (lane == 0)  up = (w > 0) ? s_bot[buf][w - 1][i] : 0u;
            if (lane == 31) dn = (w < MWARPS - 1) ? s_top[buf][w + 1][i] : 0u;
            cur[i] = hor[i] | up | dn;
        }
        if (interior) {
            #pragma unroll
            for (int i = 0; i < 16; i++) notcov += __popc(tgt[i] & ~cur[i]);
        }
    }

    // warp reduce
    #pragma unroll
    for (int o = 16; o; o >>= 1) {
        notcov += __shfl_down_sync(0xffffffffu, notcov, o);
        cnt    += __shfl_down_sync(0xffffffffu, cnt, o);
    }
    __shared__ int sred[MWARPS][2];
    if (lane == 0) { sred[w][0] = notcov; sred[w][1] = cnt; }
    __syncthreads();
    if (threadIdx.x == 0) {
        int N = 0, C = 0;
        #pragma unroll
        for (int i = 0; i < MWARPS; i++) { N += sred[i][0]; C += sred[i][1]; }
        g_mds [b][dir][band] = C + N;   // telescoped distance sum
        g_mcnt[b][dir][band] = C;
    }

    // ---- last-block finalize ----
    __shared__ bool isLast;
    __syncthreads();
    if (threadIdx.x == 0) {
        __threadfence();
        int old = atomicAdd(&g_done, 1);
        isLast = (old == MEDIAL_BLOCKS - 1);
    }
    __syncthreads();
    if (!isLast) return;
    __threadfence();

    __shared__ float acc[B][12];
    __shared__ float sd[B], ss[B], sm2[B];
    int t = threadIdx.x;
    for (int idx = t; idx < B * 12; idx += 320) {
        int bb = idx / 12, k = idx % 12;
        float s = 0.f;
        #pragma unroll
        for (int i = 0; i < GX; i++) s += g_part[i][bb][k];
        acc[bb][k] = s;
    }
    __syncthreads();

    if (t < B) {
        int bb = t;
        float inter = acc[bb][0], ps = acc[bb][1], gs = acc[bb][2];
        float dice = (2.f * inter + 1.f) / (ps + gs + 1.f);

        float pe = acc[bb][3],  ge = acc[bb][4],  ie = acc[bb][5];
        float pm = acc[bb][6],  gm = acc[bb][7],  im = acc[bb][8];
        float pj = acc[bb][9],  gj = acc[bb][10], ij = acc[bb][11];
        float e_iou = (ie + 1.f) / (pe + ge - ie + 1.f);
        float m_iou = (im + 1.f) / (pm + gm - im + 1.f);
        float j_iou = (ij + 1.f) / (pj + gj - ij + 1.f);
        float total = ge + gj + gm + 1.f;
        float sl = 1.f - ((ge / total) * e_iou + (gj / total) * j_iou + (gm / total) * m_iou);

        int ds0 = 0, ds1 = 0, c0 = 0, c1 = 0;
        #pragma unroll
        for (int i = 0; i < MNB; i++) {
            ds0 += g_mds[bb][0][i];  c0 += g_mcnt[bb][0][i];
            ds1 += g_mds[bb][1][i];  c1 += g_mcnt[bb][1][i];
        }
        float p2g = (float)ds0 / ((float)c0 + 1.f);
        float g2p = (float)ds1 / ((float)c1 + 1.f);
        float med = ((p2g + g2p) * 0.5f) / 10.f;

        sd[bb] = dice; ss[bb] = sl; sm2[bb] = med;
    }
    __syncthreads();

    if (t == 0) {
        float d = 0.f, s = 0.f, m = 0.f;
        for (int i = 0; i < B; i++) { d += sd[i]; s += ss[i]; m += sm2[i]; }
        d *= (1.f / B); s *= (1.f / B); m *= (1.f / B);
        float dl = 1.f - d;
        float avg = (dl + s + m) / 3.f;
        out[0] = dl / (dl + 1.f) * avg + s / (s + 1.f) * avg + m / (m + 1.f) * avg;
        g_done = 0;                              // reset for next graph replay
    }
}

extern "C" void kernel_launch(void* const* d_in, const int* in_sizes, int n_in,
                              void* d_out, int out_size) {
    const float* pred = (const float*)d_in[0];
    const float* gt   = (const float*)d_in[1];
    float* out = (float*)d_out;
    (void)in_sizes; (void)n_in; (void)out_size;

    stats_kernel<<<dim3(GX, B), 128>>>(pred, gt);
    medial_kernel<<<dim3(MNB, B * 2), 320>>>(out);
}